// round 6
// baseline (speedup 1.0000x reference)
#include <cuda_runtime.h>
#include <cuda_fp16.h>
#include <cooperative_groups.h>
#include <cstdint>

namespace cg = cooperative_groups;

#define BB 32
#define T_ENC 800
#define T_DEC 400
#define EDIM 256
#define GDIM 256
#define ADIM 128
#define IDIM 80
#define CL 4              // cluster size (CTAs per batch element)
#define GSL (GDIM / CL)   // 64 hidden units per rank
#define TSL (T_ENC / CL)  // 200 encoder steps per rank
#define OSL (IDIM / CL)   // 20 output rows per rank
#define NROWS (3 * GSL)   // 192 GRU rows per rank

// Scratch (allocation-free: __device__ globals)
__device__ __align__(16) float  g_gx[BB * T_DEC * 3 * GDIM];     // 39.3 MB
__device__ __align__(16) __half g_wih_h[3 * GDIM * EDIM];        // fp16 ctx-part of W_ih
__device__ __align__(16) __half g_whh_h[3 * GDIM * GDIM];        // fp16 W_hh
__device__ __align__(16) __half g_ep_h[BB * T_ENC * ADIM];       // fp16 enc_proj (6.6 MB)
__device__ __align__(16) __half g_ef_h[BB * T_ENC * EDIM];       // fp16 enc_feat (13.1 MB)
__device__ __align__(16) __half g_wdec_h[ADIM * GDIM];           // fp16 W_dec
__device__ __align__(16) __half g_wout_h[IDIM * (GDIM + EDIM)];  // fp16 W_out

#define SMEM_DYN (2 * NROWS * 256 * (int)sizeof(__half))         // 192 KB

__device__ __forceinline__ float fast_tanh(float x) {
    float y;
    asm("tanh.approx.f32 %0, %1;" : "=f"(y) : "f"(x));
    return y;
}
__device__ __forceinline__ float fast_sig(float x) {
    return 0.5f * fast_tanh(0.5f * x) + 0.5f;
}

// ---------------------------------------------------------------------------
__global__ void convert_weights(const float* __restrict__ W_ih,
                                const float* __restrict__ W_hh)
{
    const int i = blockIdx.x * blockDim.x + threadIdx.x;
    if (i < 3 * GDIM * EDIM) {
        const int r = i >> 8, c = i & 255;
        g_wih_h[i] = __float2half(W_ih[(size_t)r * 336 + 80 + c]);
        g_whh_h[i] = __float2half(W_hh[i]);
    }
}

__global__ void convert_aux(const float* __restrict__ W_dec,
                            const float* __restrict__ W_out,
                            const float* __restrict__ enc_feat)
{
    const size_t n_ef = (size_t)BB * T_ENC * EDIM;
    const int n_wd = ADIM * GDIM;
    const int n_wo = IDIM * (GDIM + EDIM);
    for (size_t i = (size_t)blockIdx.x * blockDim.x + threadIdx.x;
         i < n_ef; i += (size_t)gridDim.x * blockDim.x) {
        g_ef_h[i] = __float2half(enc_feat[i]);
        if (i < (size_t)n_wd) g_wdec_h[i] = __float2half(W_dec[i]);
        if (i < (size_t)n_wo) g_wout_h[i] = __float2half(W_out[i]);
    }
}

// ---------------------------------------------------------------------------
// Tiled GEMM: C[M,N] = A[M,K] @ B[N,K]^T, fp32 out
// ---------------------------------------------------------------------------
__global__ void gemm_abt(const float* __restrict__ Ap, const float* __restrict__ Bp,
                         float* __restrict__ Cp,
                         int M, int N, int K, int lda, int ldb, int ldc)
{
    __shared__ float As[64][33];
    __shared__ float Bs[128][33];
    const int tb_m = blockIdx.y * 64;
    const int tb_n = blockIdx.x * 128;
    const int tid  = threadIdx.x;
    const int col  = tid & 127;
    const int rg   = tid >> 7;

    float acc[32];
#pragma unroll
    for (int r = 0; r < 32; r++) acc[r] = 0.f;

    for (int k0 = 0; k0 < K; k0 += 32) {
        const int kw = (K - k0 < 32) ? (K - k0) : 32;
        for (int i = tid; i < 64 * 32; i += 256) {
            int r = i >> 5, c = i & 31;
            As[r][c] = (c < kw) ? Ap[(size_t)(tb_m + r) * lda + k0 + c] : 0.f;
        }
        for (int i = tid; i < 128 * 32; i += 256) {
            int r = i >> 5, c = i & 31;
            Bs[r][c] = (c < kw) ? Bp[(size_t)(tb_n + r) * ldb + k0 + c] : 0.f;
        }
        __syncthreads();
#pragma unroll
        for (int kk = 0; kk < 32; kk++) {
            float bv = Bs[col][kk];
#pragma unroll
            for (int r = 0; r < 32; r++)
                acc[r] += As[rg * 32 + r][kk] * bv;
        }
        __syncthreads();
    }
#pragma unroll
    for (int r = 0; r < 32; r++)
        Cp[(size_t)(tb_m + rg * 32 + r) * ldc + tb_n + col] = acc[r];
}

// Same GEMM but writes fp16 (for enc_proj)
__global__ void gemm_abt_h(const float* __restrict__ Ap, const float* __restrict__ Bp,
                           __half* __restrict__ Cp,
                           int M, int N, int K, int lda, int ldb, int ldc)
{
    __shared__ float As[64][33];
    __shared__ float Bs[128][33];
    const int tb_m = blockIdx.y * 64;
    const int tb_n = blockIdx.x * 128;
    const int tid  = threadIdx.x;
    const int col  = tid & 127;
    const int rg   = tid >> 7;

    float acc[32];
#pragma unroll
    for (int r = 0; r < 32; r++) acc[r] = 0.f;

    for (int k0 = 0; k0 < K; k0 += 32) {
        const int kw = (K - k0 < 32) ? (K - k0) : 32;
        for (int i = tid; i < 64 * 32; i += 256) {
            int r = i >> 5, c = i & 31;
            As[r][c] = (c < kw) ? Ap[(size_t)(tb_m + r) * lda + k0 + c] : 0.f;
        }
        for (int i = tid; i < 128 * 32; i += 256) {
            int r = i >> 5, c = i & 31;
            Bs[r][c] = (c < kw) ? Bp[(size_t)(tb_n + r) * ldb + k0 + c] : 0.f;
        }
        __syncthreads();
#pragma unroll
        for (int kk = 0; kk < 32; kk++) {
            float bv = Bs[col][kk];
#pragma unroll
            for (int r = 0; r < 32; r++)
                acc[r] += As[rg * 32 + r][kk] * bv;
        }
        __syncthreads();
    }
#pragma unroll
    for (int r = 0; r < 32; r++)
        Cp[(size_t)(tb_m + rg * 32 + r) * ldc + tb_n + col] = __float2half(acc[r]);
}

// ---------------------------------------------------------------------------
// Clustered persistent decode: 4 CTAs per batch element, 1024 threads each.
// 3 cluster syncs/step. All big streams fp16.
// ---------------------------------------------------------------------------
__global__ void __launch_bounds__(1024, 1) __cluster_dims__(CL, 1, 1)
decode_kernel(
    const float* __restrict__ b_ih, const float* __restrict__ b_hh,
    const float* __restrict__ b_attn, const float* __restrict__ v_attn,
    const float* __restrict__ b_out,
    float* __restrict__ pred_out, float* __restrict__ attn_out)
{
    cg::cluster_group clu = cg::this_cluster();
    const int rank = (int)clu.block_rank();
    const int b    = blockIdx.x / CL;
    const int tid  = threadIdx.x;
    const int lane = tid & 31;
    const int w    = tid >> 5;

    extern __shared__ __align__(16) __half s_wdyn[];
    __half* s_wih = s_wdyn;                 // [NROWS][256]
    __half* s_whh = s_wdyn + NROWS * 256;   // [NROWS][256]

    __shared__ __align__(16) float s_hbuf[2][GDIM];
    __shared__ __align__(16) float s_ctx[EDIM];
    __shared__ __align__(16) __half2 s_hh2[GDIM / 2];
    __shared__ __align__(16) __half2 s_ch2[EDIM / 2];
    __shared__ __align__(16) float s_grz[2 * GSL];
    __shared__ __align__(16) float s_gni[GSL];
    __shared__ __align__(16) float s_gnh[GSL];
    __shared__ __align__(16) float s_gx[NROWS];
    __shared__ __align__(16) float s_brz[2 * GSL];
    __shared__ __align__(16) float s_bni[GSL], s_bnh[GSL];
    __shared__ __align__(16) float s_battn[ADIM];
    __shared__ __align__(16) float s_boutv[OSL];
    __shared__ __align__(16) float s_dp[ADIM];
    __shared__ __align__(16) float s_e[TSL];
    __shared__ __align__(16) float s_ctxp[16][EDIM];
    __shared__ __align__(16) float s_ctxpart[CL][EDIM];
    __shared__ __align__(16) float s_logits[OSL];
    __shared__ float s_red[32];
    __shared__ float s_bmax, s_bsum;
    __shared__ float s_ms[CL][2];
    __shared__ float s_oms[CL][2];

    // ---- one-time init ----------------------------------------------------
#pragma unroll
    for (int g = 0; g < 3; g++) {
        const uint4* src_i = (const uint4*)(g_wih_h + (size_t)(g * GDIM + GSL * rank) * 256);
        const uint4* src_h = (const uint4*)(g_whh_h + (size_t)(g * GDIM + GSL * rank) * 256);
        uint4* dst_i = (uint4*)(s_wih + (size_t)g * GSL * 256);
        uint4* dst_h = (uint4*)(s_whh + (size_t)g * GSL * 256);
        for (int i = tid; i < GSL * 256 / 8; i += 1024) {
            dst_i[i] = src_i[i];
            dst_h[i] = src_h[i];
        }
    }
    if (tid < GSL) {
        const int u = tid;
#pragma unroll
        for (int g = 0; g < 2; g++) {
            const int row = g * GDIM + GSL * rank + u;
            s_brz[g * GSL + u] = b_ih[row] + b_hh[row];
        }
        const int rown = 2 * GDIM + GSL * rank + u;
        s_bni[u] = b_ih[rown];
        s_bnh[u] = b_hh[rown];
    }
    if (tid < ADIM) s_battn[tid] = b_attn[tid];
    if (tid < OSL)  s_boutv[tid] = b_out[OSL * rank + tid];
    if (tid < GDIM) s_hbuf[0][tid] = 0.f;
    if (tid < EDIM) s_ctx[tid] = 0.f;
    if (tid < 128) { s_hh2[tid] = __half2half2(__float2half(0.f));
                     s_ch2[tid] = __half2half2(__float2half(0.f)); }
    {
        const float* gx0 = g_gx + (size_t)(b * T_DEC) * 768;
        if (tid < NROWS) {
            const int g = tid / GSL, u = tid % GSL;
            s_gx[tid] = gx0[g * GDIM + GSL * rank + u];
        }
    }
    clu.sync();

    const float4 vreg = ((const float4*)v_attn)[lane];
    const int tbase = TSL * rank;

    for (int t = 0; t < T_DEC; t++) {
        const int cb = t & 1, nb = cb ^ 1;

        // ---- A: GRU GEMV from SMEM fp16 weights ---------------------------
        {
            const __half2 xi0 = s_ch2[lane * 4 + 0], xi1 = s_ch2[lane * 4 + 1];
            const __half2 xi2 = s_ch2[lane * 4 + 2], xi3 = s_ch2[lane * 4 + 3];
            const __half2 xh0 = s_hh2[lane * 4 + 0], xh1 = s_hh2[lane * 4 + 1];
            const __half2 xh2 = s_hh2[lane * 4 + 2], xh3 = s_hh2[lane * 4 + 3];
#pragma unroll
            for (int rr = 0; rr < 6; rr++) {
                const int u = 2 * w + (rr & 1);
                const int g = rr >> 1;
                const int lr = g * GSL + u;
                const uint4 wv = *(const uint4*)(s_wih + (size_t)lr * 256 + lane * 8);
                const uint4 uv = *(const uint4*)(s_whh + (size_t)lr * 256 + lane * 8);
                const __half2 w0 = *(const __half2*)&wv.x, w1 = *(const __half2*)&wv.y;
                const __half2 w2 = *(const __half2*)&wv.z, w3 = *(const __half2*)&wv.w;
                const __half2 u0 = *(const __half2*)&uv.x, u1 = *(const __half2*)&uv.y;
                const __half2 u2 = *(const __half2*)&uv.z, u3 = *(const __half2*)&uv.w;
                __half2 pa = __hfma2(w1, xi1, __hmul2(w0, xi0));
                __half2 pb = __hfma2(w3, xi3, __hmul2(w2, xi2));
                __half2 qa = __hfma2(u1, xh1, __hmul2(u0, xh0));
                __half2 qb = __hfma2(u3, xh3, __hmul2(u2, xh2));
                const float2 fa = __half22float2(pa), fb = __half22float2(pb);
                const float2 ga = __half22float2(qa), gb = __half22float2(qb);
                float a1 = (fa.x + fa.y) + (fb.x + fb.y);
                float a2 = (ga.x + ga.y) + (gb.x + gb.y);
                if (g < 2) {
                    float a = a1 + a2;
#pragma unroll
                    for (int o = 16; o > 0; o >>= 1)
                        a += __shfl_xor_sync(0xffffffffu, a, o);
                    if (lane == 0) s_grz[lr] = a + s_gx[lr] + s_brz[lr];
                } else {
#pragma unroll
                    for (int o = 16; o > 0; o >>= 1) {
                        a1 += __shfl_xor_sync(0xffffffffu, a1, o);
                        a2 += __shfl_xor_sync(0xffffffffu, a2, o);
                    }
                    if (lane == 0) {
                        s_gni[u] = a1 + s_gx[lr] + s_bni[u];
                        s_gnh[u] = a2 + s_bnh[u];
                    }
                }
            }
        }
        __syncthreads();

        // ---- gates -> h_new slice, broadcast to all cluster CTAs ----------
        if (tid < GSL) {
            const int u = tid;
            const float r = fast_sig(s_grz[u]);
            const float z = fast_sig(s_grz[GSL + u]);
            const float n = fast_tanh(s_gni[u] + r * s_gnh[u]);
            const float hn = (1.f - z) * n + z * s_hbuf[cb][GSL * rank + u];
#pragma unroll
            for (int p = 0; p < CL; p++)
                *clu.map_shared_rank(&s_hbuf[nb][GSL * rank + u], p) = hn;
        }
        clu.sync();   // #1: full h_new visible everywhere

        // ---- B: full dec_proj locally (128 rows, 8 lanes/row, fp16 W) -----
        {
            const int row = tid >> 3;     // 0..127
            const int sl8 = tid & 7;
            const uint4* wd = (const uint4*)(g_wdec_h + (size_t)row * 256 + sl8 * 32);
            const float4* hb = (const float4*)(&s_hbuf[nb][sl8 * 32]);
            float a = 0.f;
#pragma unroll
            for (int i = 0; i < 4; i++) {
                const uint4 wv = wd[i];
                const float4 x0 = hb[2 * i], x1 = hb[2 * i + 1];
                const float2 w0 = __half22float2(*(const __half2*)&wv.x);
                const float2 w1 = __half22float2(*(const __half2*)&wv.y);
                const float2 w2 = __half22float2(*(const __half2*)&wv.z);
                const float2 w3 = __half22float2(*(const __half2*)&wv.w);
                a += w0.x * x0.x + w0.y * x0.y + w1.x * x0.z + w1.y * x0.w
                   + w2.x * x1.x + w2.y * x1.y + w3.x * x1.z + w3.y * x1.w;
            }
            a += __shfl_xor_sync(0xffffffffu, a, 4);
            a += __shfl_xor_sync(0xffffffffu, a, 2);
            a += __shfl_xor_sync(0xffffffffu, a, 1);
            if (sl8 == 0) s_dp[row] = a + s_battn[row];
        }
        __syncthreads();

        // ---- C: scores, 7-way unrolled, fp16 ep ---------------------------
        {
            const float4 dpv = ((const float4*)s_dp)[lane];
            uint2 er[7];
#pragma unroll
            for (int k = 0; k < 7; k++) {
                const int tt = w + k * 32;
                if (tt < TSL)
                    er[k] = *(const uint2*)(g_ep_h +
                        ((size_t)(b * T_ENC + tbase + tt) * 128 + lane * 4));
            }
#pragma unroll
            for (int k = 0; k < 7; k++) {
                const int tt = w + k * 32;
                if (tt < TSL) {
                    const float2 f0 = __half22float2(*(const __half2*)&er[k].x);
                    const float2 f1 = __half22float2(*(const __half2*)&er[k].y);
                    float acc = fast_tanh(f0.x + dpv.x) * vreg.x
                              + fast_tanh(f0.y + dpv.y) * vreg.y
                              + fast_tanh(f1.x + dpv.z) * vreg.z
                              + fast_tanh(f1.y + dpv.w) * vreg.w;
#pragma unroll
                    for (int o = 16; o > 0; o >>= 1)
                        acc += __shfl_xor_sync(0xffffffffu, acc, o);
                    if (lane == 0) s_e[tt] = acc;
                }
            }
        }
        __syncthreads();

        // local softmax stats (200 values)
        float v = (tid < TSL) ? s_e[tid] : -1e30f;
#pragma unroll
        for (int o = 16; o > 0; o >>= 1) v = fmaxf(v, __shfl_xor_sync(0xffffffffu, v, o));
        if (lane == 0) s_red[w] = v;
        __syncthreads();
        if (w == 0) {
            float mm = s_red[lane];
#pragma unroll
            for (int o = 16; o > 0; o >>= 1) mm = fmaxf(mm, __shfl_xor_sync(0xffffffffu, mm, o));
            if (lane == 0) s_bmax = mm;
        }
        __syncthreads();
        const float m_r = s_bmax;
        float ex = 0.f;
        if (tid < TSL) { ex = __expf(s_e[tid] - m_r); s_e[tid] = ex; }
#pragma unroll
        for (int o = 16; o > 0; o >>= 1) ex += __shfl_xor_sync(0xffffffffu, ex, o);
        if (lane == 0) s_red[w] = ex;
        __syncthreads();
        if (w == 0) {
            float ss = s_red[lane];
#pragma unroll
            for (int o = 16; o > 0; o >>= 1) ss += __shfl_xor_sync(0xffffffffu, ss, o);
            if (lane == 0) s_bsum = ss;
        }
        __syncthreads();

        // ---- D: local ctx partial, fp16 ef --------------------------------
        {
            const int q  = tid >> 6;
            const int c4 = tid & 63;
            float4 acc = make_float4(0.f, 0.f, 0.f, 0.f);
            for (int tt = q; tt < TSL; tt += 16) {
                const float wgt = s_e[tt];
                const uint2 ev = *(const uint2*)(g_ef_h +
                    ((size_t)(b * T_ENC + tbase + tt) * 256 + c4 * 4));
                const float2 e0 = __half22float2(*(const __half2*)&ev.x);
                const float2 e1 = __half22float2(*(const __half2*)&ev.y);
                acc.x += wgt * e0.x; acc.y += wgt * e0.y;
                acc.z += wgt * e1.x; acc.w += wgt * e1.y;
            }
            ((float4*)s_ctxp[q])[c4] = acc;
        }
        __syncthreads();
        if (tid < 64) {
            float4 r4 = make_float4(0.f, 0.f, 0.f, 0.f);
#pragma unroll
            for (int qq = 0; qq < 16; qq++) {
                const float4 p4 = ((const float4*)s_ctxp[qq])[tid];
                r4.x += p4.x; r4.y += p4.y; r4.z += p4.z; r4.w += p4.w;
            }
#pragma unroll
            for (int p = 0; p < CL; p++)
                ((float4*)clu.map_shared_rank(&s_ctxpart[rank][0], p))[tid] = r4;
        }
        if (tid == 0) {
#pragma unroll
            for (int p = 0; p < CL; p++) {
                float* d = clu.map_shared_rank(&s_ms[rank][0], p);
                d[0] = s_bmax; d[1] = s_bsum;
            }
        }
        clu.sync();   // #2: ctx partials + (m,s) pairs visible

        // ---- merge: global softmax + ctx ----------------------------------
        float M = -1e30f;
#pragma unroll
        for (int p = 0; p < CL; p++) M = fmaxf(M, s_ms[p][0]);
        float S = 0.f;
#pragma unroll
        for (int p = 0; p < CL; p++) S += s_ms[p][1] * __expf(s_ms[p][0] - M);
        const float invS = 1.f / S;
        if (tid < 64) {
            float4 r4 = make_float4(0.f, 0.f, 0.f, 0.f);
#pragma unroll
            for (int p = 0; p < CL; p++) {
                const float wp = __expf(s_ms[p][0] - M);
                const float4 p4 = ((const float4*)&s_ctxpart[p][0])[tid];
                r4.x += wp * p4.x; r4.y += wp * p4.y;
                r4.z += wp * p4.z; r4.w += wp * p4.w;
            }
            r4.x *= invS; r4.y *= invS; r4.z *= invS; r4.w *= invS;
            ((float4*)s_ctx)[tid] = r4;
        }
        // attention record slice
        {
            const float sc = __expf(m_r - M) * invS;
            if (tid < TSL / 4) {
                float4 e4 = ((const float4*)s_e)[tid];
                e4.x *= sc; e4.y *= sc; e4.z *= sc; e4.w *= sc;
                ((float4*)(attn_out + (size_t)(b * T_DEC + t) * T_ENC + tbase))[tid] = e4;
            }
        }
        __syncthreads();  // s_ctx ready for E

        // ---- E: output logits slice rows [20*rank, +20), fp16 W_out -------
        if (w < OSL) {
            const int row = OSL * rank + w;
            const float* oper = (lane < 16) ? &s_hbuf[nb][lane * 16]
                                            : &s_ctx[(lane - 16) * 16];
            const uint4* wo = (const uint4*)(g_wout_h + (size_t)row * 512 + lane * 16);
            float acc = 0.f;
#pragma unroll
            for (int i = 0; i < 2; i++) {
                const uint4 wv = wo[i];
                const float4 x0 = ((const float4*)oper)[2 * i];
                const float4 x1 = ((const float4*)oper)[2 * i + 1];
                const float2 w0 = __half22float2(*(const __half2*)&wv.x);
                const float2 w1 = __half22float2(*(const __half2*)&wv.y);
                const float2 w2 = __half22float2(*(const __half2*)&wv.z);
                const float2 w3 = __half22float2(*(const __half2*)&wv.w);
                acc += w0.x * x0.x + w0.y * x0.y + w1.x * x0.z + w1.y * x0.w
                     + w2.x * x1.x + w2.y * x1.y + w3.x * x1.z + w3.y * x1.w;
            }
#pragma unroll
            for (int o = 16; o > 0; o >>= 1) acc += __shfl_xor_sync(0xffffffffu, acc, o);
            if (lane == 0) s_logits[w] = acc + s_boutv[w];
        }
        __syncthreads();
        if (w == 0) {
            float lv = (lane < OSL) ? s_logits[lane] : -1e30f;
            float lm = lv;
#pragma unroll
            for (int o = 16; o > 0; o >>= 1) lm = fmaxf(lm, __shfl_xor_sync(0xffffffffu, lm, o));
            float le = (lane < OSL) ? __expf(lv - lm) : 0.f;
#pragma unroll
            for (int o = 16; o > 0; o >>= 1) le += __shfl_xor_sync(0xffffffffu, le, o);
            if (lane == 0) {
#pragma unroll
                for (int p = 0; p < CL; p++) {
                    float* d = clu.map_shared_rank(&s_oms[rank][0], p);
                    d[0] = lm; d[1] = le;
                }
            }
        }
        clu.sync();   // #3: logit (m,s) pairs visible
        if (w == 0) {
            float M2 = -1e30f;
#pragma unroll
            for (int p = 0; p < CL; p++) M2 = fmaxf(M2, s_oms[p][0]);
            float S2 = 0.f;
#pragma unroll
            for (int p = 0; p < CL; p++) S2 += s_oms[p][1] * __expf(s_oms[p][0] - M2);
            const float off = M2 + __logf(S2);
            if (lane < OSL)
                pred_out[(size_t)(b * T_DEC + t) * IDIM + OSL * rank + lane] =
                    s_logits[lane] - off;
        }

        // ---- prefetch/convert for next step -------------------------------
        if (tid < 128) {
            s_hh2[tid] = __floats2half2_rn(s_hbuf[nb][2 * tid], s_hbuf[nb][2 * tid + 1]);
            s_ch2[tid] = __floats2half2_rn(s_ctx[2 * tid], s_ctx[2 * tid + 1]);
        }
        if (t + 1 < T_DEC && tid < NROWS) {
            const float* gxn = g_gx + (size_t)(b * T_DEC + t + 1) * 768;
            const int g = tid / GSL, u = tid % GSL;
            s_gx[tid] = gxn[g * GDIM + GSL * rank + u];
        }
        __syncthreads();
    }
}

// ---------------------------------------------------------------------------
extern "C" void kernel_launch(void* const* d_in, const int* in_sizes, int n_in,
                              void* d_out, int out_size)
{
    const float* enc_feat = (const float*)d_in[0];
    const float* gt       = (const float*)d_in[1];
    const float* W_ih     = (const float*)d_in[2];
    const float* W_hh     = (const float*)d_in[3];
    const float* b_ih     = (const float*)d_in[4];
    const float* b_hh     = (const float*)d_in[5];
    const float* W_enc    = (const float*)d_in[6];
    const float* W_dec    = (const float*)d_in[7];
    const float* b_attn   = (const float*)d_in[8];
    const float* v_attn   = (const float*)d_in[9];
    const float* W_out    = (const float*)d_in[10];
    const float* b_out    = (const float*)d_in[11];

    float* pred = (float*)d_out;                              // (B, T_DEC, 80)
    float* attn = (float*)d_out + (size_t)BB * T_DEC * IDIM;  // (B, T_DEC, 800)

    __half* ep_ptr = nullptr;
    float*  gx_ptr = nullptr;
    cudaGetSymbolAddress((void**)&ep_ptr, g_ep_h);
    cudaGetSymbolAddress((void**)&gx_ptr, g_gx);

    static bool attr_set = false;
    if (!attr_set) {
        cudaFuncSetAttribute(decode_kernel,
                             cudaFuncAttributeMaxDynamicSharedMemorySize, SMEM_DYN);
        attr_set = true;
    }

    convert_weights<<<(3 * GDIM * EDIM + 255) / 256, 256>>>(W_ih, W_hh);
    convert_aux<<<2048, 256>>>(W_dec, W_out, enc_feat);
    // enc_proj (fp16 out): (25600, 128) = enc_feat(25600,256) @ W_enc(128,256)^T
    gemm_abt_h<<<dim3(1, 400), 256>>>(enc_feat, W_enc, ep_ptr,
                                      BB * T_ENC, ADIM, EDIM, EDIM, EDIM, ADIM);
    // gx: (12800, 768) = gt(12800,80) @ W_ih[:, :80](768-row, ld=336)^T
    gemm_abt<<<dim3(6, 200), 256>>>(gt, W_ih, gx_ptr,
                                    BB * T_DEC, 3 * GDIM, IDIM, IDIM, 336, 3 * GDIM);

    decode_kernel<<<BB * CL, 1024, SMEM_DYN>>>(b_ih, b_hh, b_attn, v_attn, b_out,
                                               pred, attn);
}